// round 3
// baseline (speedup 1.0000x reference)
#include <cuda_runtime.h>

// Problem constants (from reference setup_inputs)
#define B_TOT 4096
#define N_IN  512
#define N_TOT 2048
#define N_EV  1536
#define N_OUT 256

#define KB    128          // eval nodes per block
#define NBLK  (N_EV / KB)  // 12
#define SUB   16           // triangle sub-block
#define BT    32           // batch columns per CTA
#define NCTA  (B_TOT / BT) // 128
#define NTHR  128
#define CH    64           // p-chunk for GEMM staging

#define WSM_PAD  65        // wsm row stride  (8*65 % 32 == 8 -> conflict free)
#define WSEQ_PAD 129       // wseq row stride (8*129 % 32 == 8)
#define ZS_PAD   36        // zsm/osm_blk row stride (float4-able, 36%32=4)
#define XS_PAD   513       // xsm row stride

// smem layout (floats):
//  U (union region), 16512 floats:
//    init: xsm[32][513]
//    GEMM: wsm[128][65] + osm[64][32]
//    seq : wseq[128][129]
//  zsm[128][36], osm_blk[128][36], bias[128]
#define U_FLOATS    16512
#define SMEM_FLOATS (U_FLOATS + KB*ZS_PAD + KB*ZS_PAD + KB)

// Per-CTA-private scratch: outputs, node-major [node][batch].  32 MB.
__device__ float g_outbuf[N_TOT * B_TOT];

typedef unsigned long long ull;

// packed fp32x2 helpers (Blackwell sm_103a: PTX-only, doubles FFMA pipe rate)
__device__ __forceinline__ ull pack2(float lo, float hi) {
    ull r; asm("mov.b64 %0, {%1, %2};" : "=l"(r) : "f"(lo), "f"(hi)); return r;
}
__device__ __forceinline__ float2 unpack2(ull v) {
    float2 r; asm("mov.b64 {%0, %1}, %2;" : "=f"(r.x), "=f"(r.y) : "l"(v)); return r;
}
__device__ __forceinline__ void ffma2(ull& d, ull a, ull b) {
    asm("fma.rn.f32x2 %0, %1, %2, %0;" : "+l"(d) : "l"(a), "l"(b));
}

__device__ __forceinline__ float fast_sigmoid5(float z) {
    float t = fminf(fmaxf(5.0f * z, -60.0f), 60.0f);
    float e;
    asm("ex2.approx.f32 %0, %1;" : "=f"(e) : "f"(-t * 1.4426950408889634f));
    float d = 1.0f + e;
    float o;
    asm("rcp.approx.f32 %0, %1;" : "=f"(o) : "f"(d));
    return o;
}

extern __shared__ float smem[];

__global__ __launch_bounds__(NTHR, 1)
void neat_ff_kernel(const float* __restrict__ x,
                    const float* __restrict__ W,
                    const float* __restrict__ bias,
                    float* __restrict__ out)
{
    float* U       = smem;
    float* zsm     = smem + U_FLOATS;
    float* osm_blk = zsm + KB * ZS_PAD;
    float* bsm     = osm_blk + KB * ZS_PAD;

    const int tid = threadIdx.x;
    const int c0  = blockIdx.x * BT;

    // ---------------- init: transpose this CTA's x slice into g_outbuf ----------
    {
        float* xsm = U;
        for (int idx = tid; idx < BT * N_IN; idx += NTHR) {
            int c = idx / N_IN, p = idx % N_IN;           // coalesced read of x
            xsm[c * XS_PAD + p] = x[(c0 + c) * N_IN + p];
        }
        __syncthreads();
        for (int idx = tid; idx < BT * N_IN; idx += NTHR) {
            int c = idx % BT, p = idx / BT;               // coalesced write (128B rows)
            g_outbuf[p * B_TOT + c0 + c] = xsm[c * XS_PAD + p];
        }
        __syncthreads();
    }

    const int ng = tid >> 3;   // node group 0..15 (8 nodes each)
    const int cg = tid & 7;    // col  group 0..7  (4 cols each)

    float* wsm = U;                  // [KB][WSM_PAD]  (row-major W tile)
    float* osm = U + KB * WSM_PAD;   // [CH][BT]

    for (int t = 0; t < NBLK; ++t) {
        const int start = N_IN + t * KB;   // first global column of this block
        const int erow0 = t * KB;          // first eval row in W / bias

        // packed accumulators: acc2[k][h] = cols (cg*4 + 2h, cg*4 + 2h + 1)
        ull acc2[8][2];
        #pragma unroll
        for (int k = 0; k < 8; ++k) { acc2[k][0] = 0ull; acc2[k][1] = 0ull; }

        // stage bias for this block (visible after the first chunk barrier)
        bsm[tid] = bias[erow0 + tid];

        // -------- GEMM: acc += W[block, 0:start] * out[0:start, cols] ----------
        for (int p0 = 0; p0 < start; p0 += CH) {
            __syncthreads();  // protect prior users of U / osm, order g_outbuf writes
            for (int idx = tid; idx < KB * CH; idx += NTHR) {
                int n = idx / CH, j = idx % CH;           // coalesced 256B row reads
                wsm[n * WSM_PAD + j] = W[(erow0 + n) * N_TOT + p0 + j];
            }
            for (int idx = tid; idx < CH * BT; idx += NTHR) {
                int j = idx / BT, c = idx % BT;           // coalesced 128B rows
                osm[j * BT + c] = g_outbuf[(p0 + j) * B_TOT + c0 + c];
            }
            __syncthreads();

            #pragma unroll 2
            for (int p = 0; p < CH; ++p) {
                const ull* o2 = (const ull*)&osm[p * BT + cg * 4];
                ull ov0 = o2[0], ov1 = o2[1];
                #pragma unroll
                for (int k = 0; k < 8; ++k) {
                    float w = wsm[(ng * 8 + k) * WSM_PAD + p];
                    ull w2 = pack2(w, w);
                    ffma2(acc2[k][0], w2, ov0);
                    ffma2(acc2[k][1], w2, ov1);
                }
            }
        }
        __syncthreads();

        // -------- stage within-block W tile: [128 rows][start .. start+127] ----
        float* wseq = U;
        for (int idx = tid; idx < KB * KB; idx += NTHR) {
            int n = idx / KB, j = idx % KB;               // coalesced 512B rows
            wseq[n * WSEQ_PAD + j] = W[(erow0 + n) * N_TOT + start + j];
        }
        __syncthreads();

        // -------- hierarchical sequential solve: 8 x (16-triangle + rank-16) ---
        for (int s = 0; s < 8; ++s) {
            // owners of this sub-block dump their current z into zsm
            if ((ng >> 1) == s) {
                #pragma unroll
                for (int k = 0; k < 8; ++k) {
                    float2 a0 = unpack2(acc2[k][0]);
                    float2 a1 = unpack2(acc2[k][1]);
                    *(float2*)&zsm[(ng * 8 + k) * ZS_PAD + cg * 4]     = a0;
                    *(float2*)&zsm[(ng * 8 + k) * ZS_PAD + cg * 4 + 2] = a1;
                }
            }
            __syncthreads();

            // 16-step triangle solve, one thread per batch column
            if (tid < BT) {
                const int col  = tid;
                const int base = s * SUB;
                float oreg[SUB];
                #pragma unroll
                for (int i = 0; i < SUB; ++i) {
                    float z = zsm[(base + i) * ZS_PAD + col] + bsm[base + i];
                    #pragma unroll
                    for (int j = 0; j < i; ++j)
                        z += wseq[(base + i) * WSEQ_PAD + (base + j)] * oreg[j];
                    float o = fast_sigmoid5(z);
                    oreg[i] = o;
                    osm_blk[(base + i) * ZS_PAD + col] = o;
                }
            }
            __syncthreads();

            // rank-16 update of all later nodes in the block (packed f32x2)
            if (ng >= 2 * (s + 1)) {
                #pragma unroll
                for (int j = 0; j < SUB; ++j) {
                    const ull* o2 = (const ull*)&osm_blk[(s * SUB + j) * ZS_PAD + cg * 4];
                    ull ov0 = o2[0], ov1 = o2[1];
                    #pragma unroll
                    for (int k = 0; k < 8; ++k) {
                        float w = wseq[(ng * 8 + k) * WSEQ_PAD + s * SUB + j];
                        ull w2 = pack2(w, w);
                        ffma2(acc2[k][0], w2, ov0);
                        ffma2(acc2[k][1], w2, ov1);
                    }
                }
            }
        }
        __syncthreads();

        // -------- commit block outputs to scratch (and final output) -----------
        for (int idx = tid; idx < KB * BT; idx += NTHR) {
            int c = idx % BT, j = idx / BT;               // coalesced 128B rows
            g_outbuf[(start + j) * B_TOT + c0 + c] = osm_blk[j * ZS_PAD + c];
        }
        if (start >= N_TOT - N_OUT) {
            const int off = start - (N_TOT - N_OUT);
            for (int idx = tid; idx < KB * BT; idx += NTHR) {
                int j = idx % KB, c = idx / KB;           // coalesced along node dim
                out[(c0 + c) * N_OUT + off + j] = osm_blk[j * ZS_PAD + c];
            }
        }
        // next iteration's first chunk barrier orders these writes before reads
    }
}

extern "C" void kernel_launch(void* const* d_in, const int* in_sizes, int n_in,
                              void* d_out, int out_size)
{
    const float* x    = (const float*)d_in[0];
    const float* W    = (const float*)d_in[1];
    const float* bias = (const float*)d_in[2];
    float* out        = (float*)d_out;

    const int smem_bytes = SMEM_FLOATS * (int)sizeof(float);
    cudaFuncSetAttribute(neat_ff_kernel,
                         cudaFuncAttributeMaxDynamicSharedMemorySize, smem_bytes);
    neat_ff_kernel<<<NCTA, NTHR, smem_bytes>>>(x, W, bias, out);
}